// round 3
// baseline (speedup 1.0000x reference)
#include <cuda_runtime.h>
#include <cuda_bf16.h>
#include <cstdint>

// Problem constants (fixed by the dataset)
#define NB   2048
#define NC   9605
#define TPB  256
#define TOPK 10

#define GAMMA_NEG 4.0f
#define CLIP      0.05f
#define EPS_F     1e-8f
#define ALPHA1    2.0f
#define ALPHA_OTH 0.5f

__device__ float g_row_sums[NB];

__device__ __forceinline__ bool beats(float v, int i, float V, int I) {
    // jax.lax.top_k order: larger value first; ties -> lower index first
    return (v > V) || (v == V && i < I);
}

// base * w for a single element (exact same math as reference, f32 fast intrinsics)
__device__ __forceinline__ float elem_term(float xv, float yv) {
    float e = __expf(-xv);
    float p = __fdividef(1.0f, 1.0f + e);   // sigmoid
    if (yv != 0.0f) {
        // y=1: log(max(p,eps)) * (1-p)^1
        return __logf(fmaxf(p, EPS_F)) * (1.0f - p);
    } else {
        // y=0: log(max(xs_neg,eps)) * (1-xs_neg)^4
        float xn  = fminf(1.0f - p + CLIP, 1.0f);
        float omn = 1.0f - xn;
        float o2  = omn * omn;
        return __logf(fmaxf(xn, EPS_F)) * (o2 * o2);
    }
}

__global__ void __launch_bounds__(TPB)
row_kernel(const float* __restrict__ x, const float* __restrict__ y,
           const int* __restrict__ compost, int n_compost,
           const int* __restrict__ recycle, int n_recycle,
           const int* __restrict__ donate,  int n_donate,
           const int* __restrict__ wl_map)
{
    const int row = blockIdx.x;
    const int tid = threadIdx.x;
    const float* __restrict__ xr = x + (long long)row * NC;
    const float* __restrict__ yr = y + (long long)row * NC;

    __shared__ int   s_has[3];
    __shared__ float s_v[TPB * TOPK];
    __shared__ int   s_i[TPB * TOPK];
    __shared__ float s_sum[TPB];

    if (tid < 3) s_has[tid] = 0;
    __syncthreads();

    // per-sample ground-truth whitelist groups
    for (int k = tid; k < n_compost; k += TPB)
        if (yr[compost[k]] != 0.0f) atomicOr(&s_has[0], 1);
    for (int k = tid; k < n_recycle; k += TPB)
        if (yr[recycle[k]] != 0.0f) atomicOr(&s_has[1], 1);
    for (int k = tid; k < n_donate; k += TPB)
        if (yr[donate[k]] != 0.0f) atomicOr(&s_has[2], 1);

    // ---- main pass: sum of base*w, plus thread-local top-10 of x ----
    float tv[TOPK];
    int   ti[TOPK];
    #pragma unroll
    for (int k = 0; k < TOPK; k++) { tv[k] = __int_as_float(0xff800000); ti[k] = 0x7fffffff; }

    float sum = 0.0f;
    for (int j = tid; j < NC; j += TPB) {
        float xv = xr[j];
        float yv = yr[j];
        sum += elem_term(xv, yv);

        if (beats(xv, j, tv[TOPK-1], ti[TOPK-1])) {
            tv[TOPK-1] = xv; ti[TOPK-1] = j;
            #pragma unroll
            for (int k = TOPK - 1; k > 0; k--) {
                if (beats(tv[k], ti[k], tv[k-1], ti[k-1])) {
                    float fv = tv[k]; tv[k] = tv[k-1]; tv[k-1] = fv;
                    int   iv = ti[k]; ti[k] = ti[k-1]; ti[k-1] = iv;
                }
            }
        }
    }

    #pragma unroll
    for (int k = 0; k < TOPK; k++) {
        s_v[tid * TOPK + k] = tv[k];
        s_i[tid * TOPK + k] = ti[k];
    }
    s_sum[tid] = sum;
    __syncthreads();

    // ---- tree merge of sorted top-10 lists + tree reduce of sums ----
    for (int stride = TPB / 2; stride >= 1; stride >>= 1) {
        if (tid < stride) {
            const int ai = tid * TOPK;
            const int bi = (tid + stride) * TOPK;
            float mv[TOPK]; int mi[TOPK];
            int a = 0, b = 0;
            #pragma unroll
            for (int k = 0; k < TOPK; k++) {
                float av = s_v[ai + a]; int aidx = s_i[ai + a];
                float bv = s_v[bi + b]; int bidx = s_i[bi + b];
                if (beats(av, aidx, bv, bidx)) { mv[k] = av; mi[k] = aidx; a++; }
                else                            { mv[k] = bv; mi[k] = bidx; b++; }
            }
            #pragma unroll
            for (int k = 0; k < TOPK; k++) { s_v[ai + k] = mv[k]; s_i[ai + k] = mi[k]; }
            s_sum[tid] += s_sum[tid + stride];
        }
        __syncthreads();
    }

    // ---- serial whitelist epilogue on the top-10 (thread 0) ----
    if (tid == 0) {
        bool has1 = s_has[0] != 0, has2 = s_has[1] != 0, has3 = s_has[2] != 0;
        bool gt_only4 = !(has1 || has2 || has3);
        bool found = false;
        float mults[TOPK];
        #pragma unroll
        for (int k = 0; k < TOPK; k++) {
            int j  = s_i[k];
            int wl = wl_map[j];
            bool in_map = wl > 0;
            bool in_gt = ((wl == 1) && has1) || ((wl == 2) && has2) ||
                         ((wl == 3) && has3) || ((wl == 4) && gt_only4);
            float f = 1.0f;
            if (in_map && gt_only4)              f *= ALPHA_OTH;
            if (in_map && !in_gt && !found)      f *= ALPHA1;
            mults[k] = f;
            found = found || (in_map && in_gt);
        }
        float extra = found ? 1.0f : ALPHA1;
        float adj = 0.0f;
        #pragma unroll
        for (int k = 0; k < TOPK; k++) {
            float m = mults[k] * extra;
            if (m != 1.0f) {
                int j = s_i[k];
                adj += elem_term(xr[j], yr[j]) * (m - 1.0f);
            }
        }
        g_row_sums[row] = s_sum[0] + adj;
    }
}

__global__ void __launch_bounds__(TPB)
final_reduce_kernel(float* __restrict__ out)
{
    __shared__ float s[TPB];
    int tid = threadIdx.x;
    float sum = 0.0f;
    for (int i = tid; i < NB; i += TPB) sum += g_row_sums[i];
    s[tid] = sum;
    __syncthreads();
    for (int st = TPB / 2; st >= 1; st >>= 1) {
        if (tid < st) s[tid] += s[tid + st];
        __syncthreads();
    }
    if (tid == 0) out[0] = -s[0];
}

extern "C" void kernel_launch(void* const* d_in, const int* in_sizes, int n_in,
                              void* d_out, int out_size)
{
    const float* x       = (const float*)d_in[0];
    const float* y       = (const float*)d_in[1];
    const int*   compost = (const int*)d_in[2];
    const int*   recycle = (const int*)d_in[3];
    const int*   donate  = (const int*)d_in[4];
    const int*   wl_map  = (const int*)d_in[5];

    row_kernel<<<NB, TPB>>>(x, y,
                            compost, in_sizes[2],
                            recycle, in_sizes[3],
                            donate,  in_sizes[4],
                            wl_map);
    final_reduce_kernel<<<1, TPB>>>((float*)d_out);
}